// round 3
// baseline (speedup 1.0000x reference)
#include <cuda_runtime.h>

// ============================================================================
// GRU_Att_Layer on GB300: single persistent kernel, weight-stationary SMEM,
// software grid barrier (2 per timestep), fp32 exact.
//
// B=128, S=1024, I=256, H=256. 128 CTAs (one per SM slice, all co-resident),
// block = (row-group g = blockIdx%16) x (batch-group p = blockIdx/16, 16 batches).
//
// Per step:
//   Phase A1: 16 attention rows (K=512 over [x_t; h]) -> a -> xg   (write g_xg)
//   Phase A2: 48 w_hh rows     (K=256 over h)          -> gh       (write g_gh)
//   -- grid barrier --
//   Phase C : 48 w_ih rows (gate triples j,j+256,j+512, K=256 over xg)
//             -> r,z,n -> h_new (write g_h, out)
//   -- grid barrier --
// Weights live in SMEM for the whole kernel (~131 KB/block): zero per-step
// weight traffic. Activation traffic ~6 MB/step chip-wide (L2-resident).
// ============================================================================

#define S_LEN 1024
#define B_SZ  128
#define I_SZ  256
#define H_SZ  256
#define TH3   768

#define NBLK  128
#define NTHR  256

#define ATT_ROWS 16   // attention rows per block  (16 groups * 16 = 256)
#define HH_ROWS  48   // w_hh rows per block       (16 groups * 48 = 768)
#define JROWS    16   // j-indices per block (w_ih gate triples)
#define BB       16   // batches per block          (8 groups * 16 = 128)

#define PK5 516       // padded 512-float row (516*4 B, 16B aligned, odd bank phase)
#define PK2 260       // padded 256-float row

// shared-memory layout (float offsets)
#define OFF_WA1 0
#define OFF_Z   (OFF_WA1 + ATT_ROWS*PK5)     //  8256
#define OFF_WA2 (OFF_Z   + BB*PK5)           // 16512
#define OFF_WC  (OFF_WA2 + HH_ROWS*PK2)      // 28992
#define OFF_XG  (OFF_WC  + HH_ROWS*PK2)      // 41472
#define OFF_BA  (OFF_XG  + BB*PK2)           // 45632
#define OFF_BHH (OFF_BA  + 16)
#define OFF_BIH (OFF_BHH + 48)
#define SMEM_FLOATS (OFF_BIH + 48)           // 45744 floats
#define SMEM_BYTES  (SMEM_FLOATS * 4)        // 182976 B < 227 KB opt-in max

// ---------------- scratch (device globals: no allocation allowed) -----------
__device__ float    g_h [B_SZ * H_SZ];   // current hidden state   [b][k]
__device__ float    g_xg[B_SZ * I_SZ];   // gated input            [b][i]
__device__ float    g_gh[B_SZ * TH3];    // h @ w_hh^T + b_hh      [b][r]
__device__ unsigned g_barcnt = 0;
__device__ unsigned g_bargen = 0;

// ---------------- software grid barrier (all 128 CTAs co-resident) ----------
__device__ __forceinline__ void grid_bar() {
    __syncthreads();                       // block-local writes done & visible
    if (threadIdx.x == 0) {
        __threadfence();                   // release: publish this block's STGs
        unsigned gen = *(volatile unsigned*)&g_bargen;
        if (atomicAdd(&g_barcnt, 1u) == (unsigned)(NBLK - 1)) {
            *(volatile unsigned*)&g_barcnt = 0u;
            __threadfence();
            *(volatile unsigned*)&g_bargen = gen + 1u;
        } else {
            while (*(volatile unsigned*)&g_bargen == gen) { /* spin on L2 */ }
        }
        __threadfence();                   // acquire
    }
    __syncthreads();
}

__device__ __forceinline__ float sigmoidf_(float x) {
    return 1.0f / (1.0f + __expf(-x));
}
__device__ __forceinline__ float hsum4(float4 v) {
    return (v.x + v.y) + (v.z + v.w);
}

__global__ void __launch_bounds__(NTHR, 1)
gru_att_persistent(const float* __restrict__ x,      // [B,S,I]
                   const float* __restrict__ hid,    // [B,H]
                   const float* __restrict__ W_att,  // [I, I+H] = [256,512]
                   const float* __restrict__ b_att,  // [256]
                   const float* __restrict__ w_ih,   // [768,256]
                   const float* __restrict__ b_ih,   // [768]
                   const float* __restrict__ w_hh,   // [768,256]
                   const float* __restrict__ b_hh,   // [768]
                   float* __restrict__ out)          // [B,S,H]
{
    extern __shared__ float sm[];
    const int tid = threadIdx.x;
    const int g   = blockIdx.x & 15;   // row group   (0..15)
    const int p   = blockIdx.x >> 4;   // batch group (0..7)

    float* wa1 = sm + OFF_WA1;   // [16][516]  W_att rows (K=512)
    float* zs  = sm + OFF_Z;     // [16][516]  per-batch [x_t ; h]
    float* wa2 = sm + OFF_WA2;   // [48][260]  w_hh rows
    float* wc  = sm + OFF_WC;    // [48][260]  w_ih rows (gate*16 + jj)
    float* xgs = sm + OFF_XG;    // [16][260]  per-batch xg
    float* ba  = sm + OFF_BA;    // [16]
    float* bhh = sm + OFF_BHH;   // [48]
    float* bih = sm + OFF_BIH;   // [48]

    // ---- load weight slices into SMEM (once) ----
    for (int idx = tid; idx < ATT_ROWS * 512; idx += NTHR) {
        int rr = idx >> 9, k = idx & 511;
        wa1[rr * PK5 + k] = W_att[(g * ATT_ROWS + rr) * 512 + k];
    }
    for (int idx = tid; idx < HH_ROWS * 256; idx += NTHR) {
        int rl = idx >> 8, k = idx & 255;
        wa2[rl * PK2 + k] = w_hh[(g * HH_ROWS + rl) * 256 + k];
    }
    for (int idx = tid; idx < HH_ROWS * 256; idx += NTHR) {
        int lr = idx >> 8, k = idx & 255;
        int gate = lr >> 4, jj = lr & 15;
        wc[lr * PK2 + k] = w_ih[(gate * 256 + g * JROWS + jj) * 256 + k];
    }
    if (tid < 16) ba[tid]  = b_att[g * 16 + tid];
    if (tid < 48) bhh[tid] = b_hh[g * 48 + tid];
    if (tid < 48) {
        int gate = tid >> 4, jj = tid & 15;
        bih[tid] = b_ih[gate * 256 + g * 16 + jj];
    }

    // ---- init hidden state (deterministic every launch) ----
    g_h[blockIdx.x * 256 + tid] = hid[blockIdx.x * 256 + tid];

    // ---- prefetch x_t=0 into z x-part ----
    for (int idx = tid; idx < BB * 256; idx += NTHR) {
        int bb = idx >> 8, k = idx & 255;
        int b = p * BB + bb;
        zs[bb * PK5 + k] = x[(b * S_LEN + 0) * I_SZ + k];
    }
    grid_bar();   // h initialized everywhere, weights+x staged locally

    for (int t = 0; t < S_LEN; ++t) {
        // ---- stage h into z (h part), after previous step's barrier ----
        for (int idx = tid; idx < BB * 256; idx += NTHR) {
            int bb = idx >> 8, k = idx & 255;
            int b = p * BB + bb;
            zs[bb * PK5 + 256 + k] = g_h[b * 256 + k];
        }
        __syncthreads();

        // ================= Phase A1: attention rows (K=512) =================
        {
            const int rr = tid & 15;          // lanes 0-15: consecutive rows
            const int bb = tid >> 4;          // z reads broadcast per 16 lanes
            const float4* zp = (const float4*)(zs  + bb * PK5);
            const float4* wp = (const float4*)(wa1 + rr * PK5);
            float4 acc = make_float4(0.f, 0.f, 0.f, 0.f);
            #pragma unroll 8
            for (int kq = 0; kq < 128; ++kq) {
                float4 zv = zp[kq], wv = wp[kq];
                acc.x += zv.x * wv.x;  acc.y += zv.y * wv.y;
                acc.z += zv.z * wv.z;  acc.w += zv.w * wv.w;
            }
            float s = hsum4(acc) + ba[rr];
            float a = sigmoidf_(s);
            int i = g * 16 + rr;
            float xv = zs[bb * PK5 + i];      // x_t[b][i] (x part of z)
            int b = p * BB + bb;
            g_xg[b * 256 + i] = xv * a;       // coalesced in i per half-warp
        }

        // ================= Phase A2: w_hh rows (K=256) =======================
        {
            const int rg = tid & 15;          // rows rg, rg+16, rg+32
            const int bb = tid >> 4;
            const float4* zp = (const float4*)(zs + bb * PK5 + 256);
            const float4* w0 = (const float4*)(wa2 + rg        * PK2);
            const float4* w1 = (const float4*)(wa2 + (rg + 16) * PK2);
            const float4* w2 = (const float4*)(wa2 + (rg + 32) * PK2);
            float4 a0 = make_float4(0.f,0.f,0.f,0.f);
            float4 a1 = make_float4(0.f,0.f,0.f,0.f);
            float4 a2 = make_float4(0.f,0.f,0.f,0.f);
            #pragma unroll 8
            for (int kq = 0; kq < 64; ++kq) {
                float4 zv = zp[kq];
                float4 v0 = w0[kq], v1 = w1[kq], v2 = w2[kq];
                a0.x += zv.x * v0.x;  a0.y += zv.y * v0.y;
                a0.z += zv.z * v0.z;  a0.w += zv.w * v0.w;
                a1.x += zv.x * v1.x;  a1.y += zv.y * v1.y;
                a1.z += zv.z * v1.z;  a1.w += zv.w * v1.w;
                a2.x += zv.x * v2.x;  a2.y += zv.y * v2.y;
                a2.z += zv.z * v2.z;  a2.w += zv.w * v2.w;
            }
            int b = p * BB + bb;
            int rbase = g * 48;
            g_gh[b * 768 + rbase      + rg] = hsum4(a0) + bhh[rg];
            g_gh[b * 768 + rbase + 16 + rg] = hsum4(a1) + bhh[16 + rg];
            g_gh[b * 768 + rbase + 32 + rg] = hsum4(a2) + bhh[32 + rg];
        }

        grid_bar();   // xg / gh published

        // ---- stage xg into SMEM ----
        for (int idx = tid; idx < BB * 256; idx += NTHR) {
            int bb = idx >> 8, k = idx & 255;
            int b = p * BB + bb;
            xgs[bb * PK2 + k] = g_xg[b * 256 + k];
        }
        __syncthreads();

        // ================= Phase C: w_ih gate triples + h update ============
        {
            const int jj = tid & 15;          // lanes 0-15: consecutive j
            const int bb = tid >> 4;
            const int b  = p * BB + bb;
            const int j  = g * 16 + jj;
            // issue the small dependent loads early (L2 hits, hidden under dot)
            float ghr = g_gh[b * 768 +       j];
            float ghz = g_gh[b * 768 + 256 + j];
            float ghn = g_gh[b * 768 + 512 + j];
            float hp  = g_h [b * 256 + j];

            const float4* xp = (const float4*)(xgs + bb * PK2);
            const float4* wr = (const float4*)(wc + jj        * PK2);
            const float4* wz = (const float4*)(wc + (16 + jj) * PK2);
            const float4* wn = (const float4*)(wc + (32 + jj) * PK2);
            float4 arr = make_float4(0.f,0.f,0.f,0.f);
            float4 azz = make_float4(0.f,0.f,0.f,0.f);
            float4 ann = make_float4(0.f,0.f,0.f,0.f);
            #pragma unroll 8
            for (int kq = 0; kq < 64; ++kq) {
                float4 xv = xp[kq];
                float4 vr = wr[kq], vz = wz[kq], vn = wn[kq];
                arr.x += xv.x * vr.x;  arr.y += xv.y * vr.y;
                arr.z += xv.z * vr.z;  arr.w += xv.w * vr.w;
                azz.x += xv.x * vz.x;  azz.y += xv.y * vz.y;
                azz.z += xv.z * vz.z;  azz.w += xv.w * vz.w;
                ann.x += xv.x * vn.x;  ann.y += xv.y * vn.y;
                ann.z += xv.z * vn.z;  ann.w += xv.w * vn.w;
            }
            float gir = hsum4(arr) + bih[jj];
            float giz = hsum4(azz) + bih[16 + jj];
            float gin = hsum4(ann) + bih[32 + jj];

            float r  = sigmoidf_(gir + ghr);
            float zg = sigmoidf_(giz + ghz);
            float n  = tanhf(gin + r * ghn);
            float hn = (1.0f - zg) * n + zg * hp;

            g_h[b * 256 + j] = hn;                       // in-place, sole owner
            out[(b * S_LEN + t) * H_SZ + j] = hn;        // coalesced in j
        }

        // ---- prefetch x for t+1 (independent of h; overlaps barrier wait) ----
        if (t + 1 < S_LEN) {
            for (int idx = tid; idx < BB * 256; idx += NTHR) {
                int bb = idx >> 8, k = idx & 255;
                int b = p * BB + bb;
                zs[bb * PK5 + k] = x[(b * S_LEN + (t + 1)) * I_SZ + k];
            }
        }

        grid_bar();   // h_new published
    }
}

extern "C" void kernel_launch(void* const* d_in, const int* in_sizes, int n_in,
                              void* d_out, int out_size) {
    const float* x     = (const float*)d_in[0];
    const float* hid   = (const float*)d_in[1];
    const float* W_att = (const float*)d_in[2];
    const float* b_att = (const float*)d_in[3];
    const float* w_ih  = (const float*)d_in[4];
    const float* b_ih  = (const float*)d_in[5];
    const float* w_hh  = (const float*)d_in[6];
    const float* b_hh  = (const float*)d_in[7];
    float* out = (float*)d_out;

    // opt-in >48KB dynamic SMEM (idempotent; not a stream op, capture-safe)
    cudaFuncSetAttribute(gru_att_persistent,
                         cudaFuncAttributeMaxDynamicSharedMemorySize, SMEM_BYTES);

    gru_att_persistent<<<NBLK, NTHR, SMEM_BYTES>>>(
        x, hid, W_att, b_att, w_ih, b_ih, w_hh, b_hh, out);
}

// round 4
// speedup vs baseline: 1.3478x; 1.3478x over previous
#include <cuda_runtime.h>
#include <cstdint>

// ============================================================================
// GRU_Att_Layer, R4: persistent kernel, weight-stationary transposed SMEM,
// register-tiled 4x4 outer-product dots with packed fma.rn.f32x2 (FFMA2),
// k-split + SMEM reduction, 16-CTA batch-group barriers.
//
// B=128,S=1024,I=256,H=256. grid=128 CTAs (g=blockIdx&15 row-group,
// p=blockIdx>>4 batch-group of 16 batches), block=384 threads.
// ============================================================================

#define S_LEN 1024
#define NBLK  128
#define NTHR  384

#define ZSTR  20     // zT row stride (16 batches + 4 pad)
#define W1STR 20     // wa1T row stride (16 rows + 4 pad)
#define W2STR 52     // wa2T row stride (48 rows + 4 pad)
#define WCSTR 52
#define RT2   132    // red tile stride, A2/C: 16 vals * 8 ks + 4 pad
#define RT1   260    // red tile stride, A1 : 16 vals * 16 ks + 4 pad

// SMEM layout (float offsets)
#define OFF_W1  0                         // [512][20] W_att^T slice
#define OFF_W2  (OFF_W1 + 512*W1STR)      // 10240: [256][52] w_hh^T slice
#define OFF_WC  (OFF_W2 + 256*W2STR)      // 23552: [256][52] w_ih^T slice
#define OFF_Z   (OFF_WC + 256*WCSTR)      // 36864: [512][20] zT = [x|xg ; h]^T
#define OFF_RED (OFF_Z  + 512*ZSTR)       // 47104: partial-sum buffer (6336)
#define OFF_BA  (OFF_RED + 48*RT2)        // 53440
#define OFF_BHH (OFF_BA + 16)
#define OFF_BIH (OFF_BHH + 48)
#define SMEM_FLOATS (OFF_BIH + 48)        // 53552
#define SMEM_BYTES  (SMEM_FLOATS * 4)     // 214208 B < 227KB opt-in

// ---------------- scratch (device globals; allocation is forbidden) --------
__device__ float    g_h [128 * 256];
__device__ float    g_xg[128 * 256];
__device__ float    g_gh[128 * 768];
__device__ unsigned g_cnt[8 * 32];   // one counter per batch-group, own line
__device__ unsigned g_gen[8 * 32];

// ---------------- 16-CTA batch-group barrier --------------------------------
__device__ __forceinline__ void pbar(int grp) {
    __syncthreads();
    if (threadIdx.x == 0) {
        volatile unsigned* cnt = &g_cnt[grp * 32];
        volatile unsigned* gen = &g_gen[grp * 32];
        __threadfence();
        unsigned gv = *gen;
        if (atomicAdd((unsigned*)cnt, 1u) == 15u) {
            *cnt = 0u;
            __threadfence();
            *gen = gv + 1u;
        } else {
            while (*gen == gv) { }
        }
        __threadfence();
    }
    __syncthreads();
}

__device__ __forceinline__ float sigmoidf_(float x) {
    return 1.0f / (1.0f + __expf(-x));
}

__device__ __forceinline__ uint32_t sm_u32(const void* p) {
    uint32_t a;
    asm("{ .reg .u64 t; cvta.to.shared.u64 t, %1; cvt.u32.u64 %0, t; }"
        : "=r"(a) : "l"(p));
    return a;
}

__device__ __forceinline__ float2 unpk(unsigned long long v) {
    uint32_t lo, hi;
    asm("mov.b64 {%0,%1}, %2;" : "=r"(lo), "=r"(hi) : "l"(v));
    return make_float2(__uint_as_float(lo), __uint_as_float(hi));
}

// 32-iteration 4row x 4batch outer-product dot, packed f32x2 accumulators.
// acc[rl*2+bp] lanes = batches (4bq+2bp, 4bq+2bp+1) for row rq*4+rl.
__device__ __forceinline__ void dot32(uint32_t za, uint32_t wa,
                                      int zstep, int wstep,
                                      unsigned long long acc[8]) {
#pragma unroll 8
    for (int i = 0; i < 32; ++i) {
        unsigned long long z01, z23;
        asm volatile("ld.shared.v2.b64 {%0,%1}, [%2];"
                     : "=l"(z01), "=l"(z23) : "r"(za));
        float w0, w1, w2, w3;
        asm volatile("ld.shared.v4.f32 {%0,%1,%2,%3}, [%4];"
                     : "=f"(w0), "=f"(w1), "=f"(w2), "=f"(w3) : "r"(wa));
        unsigned long long d;
        uint32_t u;
        u = __float_as_uint(w0);
        asm("mov.b64 %0, {%1,%1};" : "=l"(d) : "r"(u));
        asm("fma.rn.f32x2 %0, %1, %2, %0;" : "+l"(acc[0]) : "l"(d), "l"(z01));
        asm("fma.rn.f32x2 %0, %1, %2, %0;" : "+l"(acc[1]) : "l"(d), "l"(z23));
        u = __float_as_uint(w1);
        asm("mov.b64 %0, {%1,%1};" : "=l"(d) : "r"(u));
        asm("fma.rn.f32x2 %0, %1, %2, %0;" : "+l"(acc[2]) : "l"(d), "l"(z01));
        asm("fma.rn.f32x2 %0, %1, %2, %0;" : "+l"(acc[3]) : "l"(d), "l"(z23));
        u = __float_as_uint(w2);
        asm("mov.b64 %0, {%1,%1};" : "=l"(d) : "r"(u));
        asm("fma.rn.f32x2 %0, %1, %2, %0;" : "+l"(acc[4]) : "l"(d), "l"(z01));
        asm("fma.rn.f32x2 %0, %1, %2, %0;" : "+l"(acc[5]) : "l"(d), "l"(z23));
        u = __float_as_uint(w3);
        asm("mov.b64 %0, {%1,%1};" : "=l"(d) : "r"(u));
        asm("fma.rn.f32x2 %0, %1, %2, %0;" : "+l"(acc[6]) : "l"(d), "l"(z01));
        asm("fma.rn.f32x2 %0, %1, %2, %0;" : "+l"(acc[7]) : "l"(d), "l"(z23));
        za += zstep;
        wa += wstep;
    }
}

__global__ void __launch_bounds__(NTHR, 1)
gru_att_persistent(const float* __restrict__ x,      // [B,S,I]
                   const float* __restrict__ hid,    // [B,H]
                   const float* __restrict__ W_att,  // [256,512]
                   const float* __restrict__ b_att,  // [256]
                   const float* __restrict__ w_ih,   // [768,256]
                   const float* __restrict__ b_ih,   // [768]
                   const float* __restrict__ w_hh,   // [768,256]
                   const float* __restrict__ b_hh,   // [768]
                   float* __restrict__ out)          // [B,S,H]
{
    extern __shared__ float smf[];
    const int tid = threadIdx.x;
    const int g   = blockIdx.x & 15;   // row group
    const int p   = blockIdx.x >> 4;   // batch group (16 batches)
    const uint32_t smb = sm_u32(smf);

    // ---- load transposed weight slices into SMEM (once) ----
    for (int idx = tid; idx < 512 * 16; idx += NTHR) {       // wa1T[k][rr]
        int k = idx >> 4, rr = idx & 15;
        smf[OFF_W1 + k * W1STR + rr] = W_att[(g * 16 + rr) * 512 + k];
    }
    for (int idx = tid; idx < 256 * 48; idx += NTHR) {       // wa2T[k][r]
        int k = idx / 48, r = idx % 48;
        smf[OFF_W2 + k * W2STR + r] = w_hh[(g * 48 + r) * 256 + k];
    }
    for (int idx = tid; idx < 256 * 48; idx += NTHR) {       // wcT[k][gate*16+jj]
        int k = idx / 48, rl = idx % 48;
        int gate = rl >> 4, jj = rl & 15;
        smf[OFF_WC + k * WCSTR + rl] = w_ih[(gate * 256 + g * 16 + jj) * 256 + k];
    }
    if (tid < 16) smf[OFF_BA + tid]  = b_att[g * 16 + tid];
    if (tid < 48) smf[OFF_BHH + tid] = b_hh[g * 48 + tid];
    if (tid < 48) {
        int gate = tid >> 4, jj = tid & 15;
        smf[OFF_BIH + tid] = b_ih[gate * 256 + g * 16 + jj];
    }

    // ---- init hidden state (one writer block per batch group) ----
    if (g == 0) {
        for (int idx = tid; idx < 16 * 256; idx += NTHR) {
            int bb = idx >> 8, k = idx & 255;
            g_h[(p * 16 + bb) * 256 + k] = hid[(p * 16 + bb) * 256 + k];
        }
    }

    // ---- prefetch x(t=0) into zT x-part ----
    for (int idx = tid; idx < 16 * 256; idx += NTHR) {
        int bb = idx >> 8, k = idx & 255;
        smf[OFF_Z + k * ZSTR + bb] = x[((p * 16 + bb) * S_LEN + 0) * 256 + k];
    }

    // ---- per-thread compute-tile constants ----
    // A1 (tid<256): 16 tiles (4rq x 4bq) x ksplit 16; tile = bq*4 + rq
    const int a1_tile = tid >> 4, a1_ks = tid & 15;
    const int a1_bq = a1_tile >> 2, a1_rq = a1_tile & 3;
    const uint32_t a1_z0 = smb + (OFF_Z + a1_ks * ZSTR + a1_bq * 4) * 4;
    const uint32_t a1_w0 = smb + (OFF_W1 + a1_ks * W1STR + a1_rq * 4) * 4;
    // A2/C (all 384): 48 tiles (12rq x 4bq) x ksplit 8; tile = bq*12 + rq
    const int t2 = tid >> 3, ks2 = tid & 7;
    const int bq2 = t2 / 12, rq2 = t2 % 12;
    const uint32_t a2_z0 = smb + (OFF_Z + (256 + ks2) * ZSTR + bq2 * 4) * 4;
    const uint32_t a2_w0 = smb + (OFF_W2 + ks2 * W2STR + rq2 * 4) * 4;
    const uint32_t c_z0  = smb + (OFF_Z + ks2 * ZSTR + bq2 * 4) * 4;
    const uint32_t c_w0  = smb + (OFF_WC + ks2 * WCSTR + rq2 * 4) * 4;

    pbar(p);   // h initialized, weights staged

    for (int t = 0; t < S_LEN; ++t) {
        // ---- stage h into zT[256+k][bb] ----
        for (int idx = tid; idx < 16 * 256; idx += NTHR) {
            int bb = idx >> 8, k = idx & 255;
            smf[OFF_Z + (256 + k) * ZSTR + bb] = g_h[(p * 16 + bb) * 256 + k];
        }
        __syncthreads();

        // ================= A1: attention rows, K=512 ====================
        if (tid < 256) {
            unsigned long long acc[8] = {0,0,0,0,0,0,0,0};
            dot32(a1_z0, a1_w0, 16 * ZSTR * 4, 16 * W1STR * 4, acc);
            float* rb = smf + OFF_RED + a1_tile * RT1 + a1_ks;
#pragma unroll
            for (int rl = 0; rl < 4; ++rl)
#pragma unroll
                for (int bp = 0; bp < 2; ++bp) {
                    float2 v = unpk(acc[rl * 2 + bp]);
                    rb[(rl * 4 + bp * 2    ) * 16] = v.x;
                    rb[(rl * 4 + bp * 2 + 1) * 16] = v.y;
                }
        }
        __syncthreads();
        if (tid < 256) {  // A1 reduce: out (rr, bb)
            int rr = tid & 15, bb = tid >> 4;
            const float* rp = smf + OFF_RED
                + ((bb >> 2) * 4 + (rr >> 2)) * RT1
                + ((rr & 3) * 4 + (bb & 3)) * 16;
            float4 q0 = *(const float4*)rp;
            float4 q1 = *(const float4*)(rp + 4);
            float4 q2 = *(const float4*)(rp + 8);
            float4 q3 = *(const float4*)(rp + 12);
            float s = ((q0.x+q0.y)+(q0.z+q0.w)) + ((q1.x+q1.y)+(q1.z+q1.w))
                    + ((q2.x+q2.y)+(q2.z+q2.w)) + ((q3.x+q3.y)+(q3.z+q3.w))
                    + smf[OFF_BA + rr];
            float a  = sigmoidf_(s);
            float xv = smf[OFF_Z + (g * 16 + rr) * ZSTR + bb];
            g_xg[(p * 16 + bb) * 256 + g * 16 + rr] = xv * a;
        }
        __syncthreads();

        // ================= A2: w_hh rows, K=256 =========================
        {
            unsigned long long acc[8] = {0,0,0,0,0,0,0,0};
            dot32(a2_z0, a2_w0, 8 * ZSTR * 4, 8 * W2STR * 4, acc);
            float* rb = smf + OFF_RED + t2 * RT2 + ks2;
#pragma unroll
            for (int rl = 0; rl < 4; ++rl)
#pragma unroll
                for (int bp = 0; bp < 2; ++bp) {
                    float2 v = unpk(acc[rl * 2 + bp]);
                    rb[(rl * 4 + bp * 2    ) * 8] = v.x;
                    rb[(rl * 4 + bp * 2 + 1) * 8] = v.y;
                }
        }
        __syncthreads();
#pragma unroll
        for (int rep = 0; rep < 2; ++rep) {  // A2 reduce: 768 outputs
            int o = tid + rep * NTHR;
            int b = o / 48, r = o % 48;
            const float* rp = smf + OFF_RED
                + ((b >> 2) * 12 + (r >> 2)) * RT2
                + ((r & 3) * 4 + (b & 3)) * 8;
            float4 q0 = *(const float4*)rp;
            float4 q1 = *(const float4*)(rp + 4);
            float s = ((q0.x+q0.y)+(q0.z+q0.w)) + ((q1.x+q1.y)+(q1.z+q1.w))
                    + smf[OFF_BHH + r];
            g_gh[(p * 16 + b) * 768 + g * 48 + r] = s;
        }

        pbar(p);   // xg / gh published within batch group

        // ---- stage xg into zT x-region (aliases x_t; A1 done with it) ----
        for (int idx = tid; idx < 16 * 256; idx += NTHR) {
            int bb = idx >> 8, k = idx & 255;
            smf[OFF_Z + k * ZSTR + bb] = g_xg[(p * 16 + bb) * 256 + k];
        }
        __syncthreads();

        // ================= C: w_ih rows over xg, K=256 ===================
        {
            unsigned long long acc[8] = {0,0,0,0,0,0,0,0};
            dot32(c_z0, c_w0, 8 * ZSTR * 4, 8 * WCSTR * 4, acc);
            float* rb = smf + OFF_RED + t2 * RT2 + ks2;
#pragma unroll
            for (int rl = 0; rl < 4; ++rl)
#pragma unroll
                for (int bp = 0; bp < 2; ++bp) {
                    float2 v = unpk(acc[rl * 2 + bp]);
                    rb[(rl * 4 + bp * 2    ) * 8] = v.x;
                    rb[(rl * 4 + bp * 2 + 1) * 8] = v.y;
                }
        }
        __syncthreads();
        if (tid < 256) {  // C reduce + gate math: out (jj, bb)
            int jj = tid & 15, bb = tid >> 4;
            int b  = p * 16 + bb;
            int j  = g * 16 + jj;
            float hp  = g_h[b * 256 + j];
            float ghr = g_gh[b * 768 + j];
            float ghz = g_gh[b * 768 + 256 + j];
            float ghn = g_gh[b * 768 + 512 + j];
            float gi[3];
#pragma unroll
            for (int gate = 0; gate < 3; ++gate) {
                int r = gate * 16 + jj;
                const float* rp = smf + OFF_RED
                    + ((bb >> 2) * 12 + (r >> 2)) * RT2
                    + ((r & 3) * 4 + (bb & 3)) * 8;
                float4 q0 = *(const float4*)rp;
                float4 q1 = *(const float4*)(rp + 4);
                gi[gate] = ((q0.x+q0.y)+(q0.z+q0.w)) + ((q1.x+q1.y)+(q1.z+q1.w))
                         + smf[OFF_BIH + r];
            }
            float r_  = sigmoidf_(gi[0] + ghr);
            float z_  = sigmoidf_(gi[1] + ghz);
            float n_  = tanhf(gi[2] + r_ * ghn);
            float hn  = (1.0f - z_) * n_ + z_ * hp;
            g_h[b * 256 + j] = hn;
            out[(b * S_LEN + t) * 256 + j] = hn;
        }

        // ---- prefetch x(t+1) into zT x-region (overlaps C-reduce / bar) ----
        if (t + 1 < S_LEN) {
            for (int idx = tid; idx < 16 * 256; idx += NTHR) {
                int bb = idx >> 8, k = idx & 255;
                smf[OFF_Z + k * ZSTR + bb] =
                    x[((p * 16 + bb) * S_LEN + (t + 1)) * 256 + k];
            }
        }

        pbar(p);   // h_new published within batch group
    }
}

extern "C" void kernel_launch(void* const* d_in, const int* in_sizes, int n_in,
                              void* d_out, int out_size) {
    const float* x     = (const float*)d_in[0];
    const float* hid   = (const float*)d_in[1];
    const float* W_att = (const float*)d_in[2];
    const float* b_att = (const float*)d_in[3];
    const float* w_ih  = (const float*)d_in[4];
    const float* b_ih  = (const float*)d_in[5];
    const float* w_hh  = (const float*)d_in[6];
    const float* b_hh  = (const float*)d_in[7];
    float* out = (float*)d_out;

    cudaFuncSetAttribute(gru_att_persistent,
                         cudaFuncAttributeMaxDynamicSharedMemorySize, SMEM_BYTES);

    gru_att_persistent<<<NBLK, NTHR, SMEM_BYTES>>>(
        x, hid, W_att, b_att, w_ih, b_ih, w_hh, b_hh, out);
}

// round 5
// speedup vs baseline: 1.3940x; 1.0343x over previous
#include <cuda_runtime.h>
#include <cstdint>

// ============================================================================
// GRU_Att_Layer, R4: persistent kernel, weight-stationary transposed SMEM,
// register-tiled 4x4 outer-product dots with packed fma.rn.f32x2 (FFMA2),
// k-split + SMEM reduction, 16-CTA batch-group barriers.
//
// B=128,S=1024,I=256,H=256. grid=128 CTAs (g=blockIdx&15 row-group,
// p=blockIdx>>4 batch-group of 16 batches), block=384 threads.
// ============================================================================

#define S_LEN 1024
#define NBLK  128
#define NTHR  384

#define ZSTR  20     // zT row stride (16 batches + 4 pad)
#define W1STR 20     // wa1T row stride (16 rows + 4 pad)
#define W2STR 52     // wa2T row stride (48 rows + 4 pad)
#define WCSTR 52
#define RT2   132    // red tile stride, A2/C: 16 vals * 8 ks + 4 pad
#define RT1   260    // red tile stride, A1 : 16 vals * 16 ks + 4 pad

// SMEM layout (float offsets)
#define OFF_W1  0                         // [512][20] W_att^T slice
#define OFF_W2  (OFF_W1 + 512*W1STR)      // 10240: [256][52] w_hh^T slice
#define OFF_WC  (OFF_W2 + 256*W2STR)      // 23552: [256][52] w_ih^T slice
#define OFF_Z   (OFF_WC + 256*WCSTR)      // 36864: [512][20] zT = [x|xg ; h]^T
#define OFF_RED (OFF_Z  + 512*ZSTR)       // 47104: partial-sum buffer (6336)
#define OFF_BA  (OFF_RED + 48*RT2)        // 53440
#define OFF_BHH (OFF_BA + 16)
#define OFF_BIH (OFF_BHH + 48)
#define SMEM_FLOATS (OFF_BIH + 48)        // 53552
#define SMEM_BYTES  (SMEM_FLOATS * 4)     // 214208 B < 227KB opt-in

// ---------------- scratch (device globals; allocation is forbidden) --------
__device__ float    g_h [128 * 256];
__device__ float    g_xg[128 * 256];
__device__ float    g_gh[128 * 768];
__device__ unsigned g_cnt[8 * 32];   // one counter per batch-group, own line
__device__ unsigned g_gen[8 * 32];

// ---------------- 16-CTA batch-group barrier --------------------------------
__device__ __forceinline__ void pbar(int grp) {
    __syncthreads();
    if (threadIdx.x == 0) {
        volatile unsigned* cnt = &g_cnt[grp * 32];
        volatile unsigned* gen = &g_gen[grp * 32];
        __threadfence();
        unsigned gv = *gen;
        if (atomicAdd((unsigned*)cnt, 1u) == 15u) {
            *cnt = 0u;
            __threadfence();
            *gen = gv + 1u;
        } else {
            while (*gen == gv) { }
        }
        __threadfence();
    }
    __syncthreads();
}

__device__ __forceinline__ float sigmoidf_(float x) {
    return 1.0f / (1.0f + __expf(-x));
}

__device__ __forceinline__ uint32_t sm_u32(const void* p) {
    uint32_t a;
    asm("{ .reg .u64 t; cvta.to.shared.u64 t, %1; cvt.u32.u64 %0, t; }"
        : "=r"(a) : "l"(p));
    return a;
}

__device__ __forceinline__ float2 unpk(unsigned long long v) {
    uint32_t lo, hi;
    asm("mov.b64 {%0,%1}, %2;" : "=r"(lo), "=r"(hi) : "l"(v));
    return make_float2(__uint_as_float(lo), __uint_as_float(hi));
}

// 32-iteration 4row x 4batch outer-product dot, packed f32x2 accumulators.
// acc[rl*2+bp] lanes = batches (4bq+2bp, 4bq+2bp+1) for row rq*4+rl.
__device__ __forceinline__ void dot32(uint32_t za, uint32_t wa,
                                      int zstep, int wstep,
                                      unsigned long long acc[8]) {
#pragma unroll 8
    for (int i = 0; i < 32; ++i) {
        unsigned long long z01, z23;
        asm volatile("ld.shared.v2.b64 {%0,%1}, [%2];"
                     : "=l"(z01), "=l"(z23) : "r"(za));
        float w0, w1, w2, w3;
        asm volatile("ld.shared.v4.f32 {%0,%1,%2,%3}, [%4];"
                     : "=f"(w0), "=f"(w1), "=f"(w2), "=f"(w3) : "r"(wa));
        unsigned long long d;
        uint32_t u;
        u = __float_as_uint(w0);
        asm("mov.b64 %0, {%1,%1};" : "=l"(d) : "r"(u));
        asm("fma.rn.f32x2 %0, %1, %2, %0;" : "+l"(acc[0]) : "l"(d), "l"(z01));
        asm("fma.rn.f32x2 %0, %1, %2, %0;" : "+l"(acc[1]) : "l"(d), "l"(z23));
        u = __float_as_uint(w1);
        asm("mov.b64 %0, {%1,%1};" : "=l"(d) : "r"(u));
        asm("fma.rn.f32x2 %0, %1, %2, %0;" : "+l"(acc[2]) : "l"(d), "l"(z01));
        asm("fma.rn.f32x2 %0, %1, %2, %0;" : "+l"(acc[3]) : "l"(d), "l"(z23));
        u = __float_as_uint(w2);
        asm("mov.b64 %0, {%1,%1};" : "=l"(d) : "r"(u));
        asm("fma.rn.f32x2 %0, %1, %2, %0;" : "+l"(acc[4]) : "l"(d), "l"(z01));
        asm("fma.rn.f32x2 %0, %1, %2, %0;" : "+l"(acc[5]) : "l"(d), "l"(z23));
        u = __float_as_uint(w3);
        asm("mov.b64 %0, {%1,%1};" : "=l"(d) : "r"(u));
        asm("fma.rn.f32x2 %0, %1, %2, %0;" : "+l"(acc[6]) : "l"(d), "l"(z01));
        asm("fma.rn.f32x2 %0, %1, %2, %0;" : "+l"(acc[7]) : "l"(d), "l"(z23));
        za += zstep;
        wa += wstep;
    }
}

__global__ void __launch_bounds__(NTHR, 1)
gru_att_persistent(const float* __restrict__ x,      // [B,S,I]
                   const float* __restrict__ hid,    // [B,H]
                   const float* __restrict__ W_att,  // [256,512]
                   const float* __restrict__ b_att,  // [256]
                   const float* __restrict__ w_ih,   // [768,256]
                   const float* __restrict__ b_ih,   // [768]
                   const float* __restrict__ w_hh,   // [768,256]
                   const float* __restrict__ b_hh,   // [768]
                   float* __restrict__ out)          // [B,S,H]
{
    extern __shared__ float smf[];
    const int tid = threadIdx.x;
    const int g   = blockIdx.x & 15;   // row group
    const int p   = blockIdx.x >> 4;   // batch group (16 batches)
    const uint32_t smb = sm_u32(smf);

    // ---- load transposed weight slices into SMEM (once) ----
    for (int idx = tid; idx < 512 * 16; idx += NTHR) {       // wa1T[k][rr]
        int k = idx >> 4, rr = idx & 15;
        smf[OFF_W1 + k * W1STR + rr] = W_att[(g * 16 + rr) * 512 + k];
    }
    for (int idx = tid; idx < 256 * 48; idx += NTHR) {       // wa2T[k][r]
        int k = idx / 48, r = idx % 48;
        smf[OFF_W2 + k * W2STR + r] = w_hh[(g * 48 + r) * 256 + k];
    }
    for (int idx = tid; idx < 256 * 48; idx += NTHR) {       // wcT[k][gate*16+jj]
        int k = idx / 48, rl = idx % 48;
        int gate = rl >> 4, jj = rl & 15;
        smf[OFF_WC + k * WCSTR + rl] = w_ih[(gate * 256 + g * 16 + jj) * 256 + k];
    }
    if (tid < 16) smf[OFF_BA + tid]  = b_att[g * 16 + tid];
    if (tid < 48) smf[OFF_BHH + tid] = b_hh[g * 48 + tid];
    if (tid < 48) {
        int gate = tid >> 4, jj = tid & 15;
        smf[OFF_BIH + tid] = b_ih[gate * 256 + g * 16 + jj];
    }

    // ---- init hidden state (one writer block per batch group) ----
    if (g == 0) {
        for (int idx = tid; idx < 16 * 256; idx += NTHR) {
            int bb = idx >> 8, k = idx & 255;
            g_h[(p * 16 + bb) * 256 + k] = hid[(p * 16 + bb) * 256 + k];
        }
    }

    // ---- prefetch x(t=0) into zT x-part ----
    for (int idx = tid; idx < 16 * 256; idx += NTHR) {
        int bb = idx >> 8, k = idx & 255;
        smf[OFF_Z + k * ZSTR + bb] = x[((p * 16 + bb) * S_LEN + 0) * 256 + k];
    }

    // ---- per-thread compute-tile constants ----
    // A1 (tid<256): 16 tiles (4rq x 4bq) x ksplit 16; tile = bq*4 + rq
    const int a1_tile = tid >> 4, a1_ks = tid & 15;
    const int a1_bq = a1_tile >> 2, a1_rq = a1_tile & 3;
    const uint32_t a1_z0 = smb + (OFF_Z + a1_ks * ZSTR + a1_bq * 4) * 4;
    const uint32_t a1_w0 = smb + (OFF_W1 + a1_ks * W1STR + a1_rq * 4) * 4;
    // A2/C (all 384): 48 tiles (12rq x 4bq) x ksplit 8; tile = bq*12 + rq
    const int t2 = tid >> 3, ks2 = tid & 7;
    const int bq2 = t2 / 12, rq2 = t2 % 12;
    const uint32_t a2_z0 = smb + (OFF_Z + (256 + ks2) * ZSTR + bq2 * 4) * 4;
    const uint32_t a2_w0 = smb + (OFF_W2 + ks2 * W2STR + rq2 * 4) * 4;
    const uint32_t c_z0  = smb + (OFF_Z + ks2 * ZSTR + bq2 * 4) * 4;
    const uint32_t c_w0  = smb + (OFF_WC + ks2 * WCSTR + rq2 * 4) * 4;

    pbar(p);   // h initialized, weights staged

    for (int t = 0; t < S_LEN; ++t) {
        // ---- stage h into zT[256+k][bb] ----
        for (int idx = tid; idx < 16 * 256; idx += NTHR) {
            int bb = idx >> 8, k = idx & 255;
            smf[OFF_Z + (256 + k) * ZSTR + bb] = g_h[(p * 16 + bb) * 256 + k];
        }
        __syncthreads();

        // ================= A1: attention rows, K=512 ====================
        if (tid < 256) {
            unsigned long long acc[8] = {0,0,0,0,0,0,0,0};
            dot32(a1_z0, a1_w0, 16 * ZSTR * 4, 16 * W1STR * 4, acc);
            float* rb = smf + OFF_RED + a1_tile * RT1 + a1_ks;
#pragma unroll
            for (int rl = 0; rl < 4; ++rl)
#pragma unroll
                for (int bp = 0; bp < 2; ++bp) {
                    float2 v = unpk(acc[rl * 2 + bp]);
                    rb[(rl * 4 + bp * 2    ) * 16] = v.x;
                    rb[(rl * 4 + bp * 2 + 1) * 16] = v.y;
                }
        }
        __syncthreads();
        if (tid < 256) {  // A1 reduce: out (rr, bb)
            int rr = tid & 15, bb = tid >> 4;
            const float* rp = smf + OFF_RED
                + ((bb >> 2) * 4 + (rr >> 2)) * RT1
                + ((rr & 3) * 4 + (bb & 3)) * 16;
            float4 q0 = *(const float4*)rp;
            float4 q1 = *(const float4*)(rp + 4);
            float4 q2 = *(const float4*)(rp + 8);
            float4 q3 = *(const float4*)(rp + 12);
            float s = ((q0.x+q0.y)+(q0.z+q0.w)) + ((q1.x+q1.y)+(q1.z+q1.w))
                    + ((q2.x+q2.y)+(q2.z+q2.w)) + ((q3.x+q3.y)+(q3.z+q3.w))
                    + smf[OFF_BA + rr];
            float a  = sigmoidf_(s);
            float xv = smf[OFF_Z + (g * 16 + rr) * ZSTR + bb];
            g_xg[(p * 16 + bb) * 256 + g * 16 + rr] = xv * a;
        }
        __syncthreads();

        // ================= A2: w_hh rows, K=256 =========================
        {
            unsigned long long acc[8] = {0,0,0,0,0,0,0,0};
            dot32(a2_z0, a2_w0, 8 * ZSTR * 4, 8 * W2STR * 4, acc);
            float* rb = smf + OFF_RED + t2 * RT2 + ks2;
#pragma unroll
            for (int rl = 0; rl < 4; ++rl)
#pragma unroll
                for (int bp = 0; bp < 2; ++bp) {
                    float2 v = unpk(acc[rl * 2 + bp]);
                    rb[(rl * 4 + bp * 2    ) * 8] = v.x;
                    rb[(rl * 4 + bp * 2 + 1) * 8] = v.y;
                }
        }
        __syncthreads();
#pragma unroll
        for (int rep = 0; rep < 2; ++rep) {  // A2 reduce: 768 outputs
            int o = tid + rep * NTHR;
            int b = o / 48, r = o % 48;
            const float* rp = smf + OFF_RED
                + ((b >> 2) * 12 + (r >> 2)) * RT2
                + ((r & 3) * 4 + (b & 3)) * 8;
            float4 q0 = *(const float4*)rp;
            float4 q1 = *(const float4*)(rp + 4);
            float s = ((q0.x+q0.y)+(q0.z+q0.w)) + ((q1.x+q1.y)+(q1.z+q1.w))
                    + smf[OFF_BHH + r];
            g_gh[(p * 16 + b) * 768 + g * 48 + r] = s;
        }

        pbar(p);   // xg / gh published within batch group

        // ---- stage xg into zT x-region (aliases x_t; A1 done with it) ----
        for (int idx = tid; idx < 16 * 256; idx += NTHR) {
            int bb = idx >> 8, k = idx & 255;
            smf[OFF_Z + k * ZSTR + bb] = g_xg[(p * 16 + bb) * 256 + k];
        }
        __syncthreads();

        // ================= C: w_ih rows over xg, K=256 ===================
        {
            unsigned long long acc[8] = {0,0,0,0,0,0,0,0};
            dot32(c_z0, c_w0, 8 * ZSTR * 4, 8 * WCSTR * 4, acc);
            float* rb = smf + OFF_RED + t2 * RT2 + ks2;
#pragma unroll
            for (int rl = 0; rl < 4; ++rl)
#pragma unroll
                for (int bp = 0; bp < 2; ++bp) {
                    float2 v = unpk(acc[rl * 2 + bp]);
                    rb[(rl * 4 + bp * 2    ) * 8] = v.x;
                    rb[(rl * 4 + bp * 2 + 1) * 8] = v.y;
                }
        }
        __syncthreads();
        if (tid < 256) {  // C reduce + gate math: out (jj, bb)
            int jj = tid & 15, bb = tid >> 4;
            int b  = p * 16 + bb;
            int j  = g * 16 + jj;
            float hp  = g_h[b * 256 + j];
            float ghr = g_gh[b * 768 + j];
            float ghz = g_gh[b * 768 + 256 + j];
            float ghn = g_gh[b * 768 + 512 + j];
            float gi[3];
#pragma unroll
            for (int gate = 0; gate < 3; ++gate) {
                int r = gate * 16 + jj;
                const float* rp = smf + OFF_RED
                    + ((bb >> 2) * 12 + (r >> 2)) * RT2
                    + ((r & 3) * 4 + (bb & 3)) * 8;
                float4 q0 = *(const float4*)rp;
                float4 q1 = *(const float4*)(rp + 4);
                gi[gate] = ((q0.x+q0.y)+(q0.z+q0.w)) + ((q1.x+q1.y)+(q1.z+q1.w))
                         + smf[OFF_BIH + r];
            }
            float r_  = sigmoidf_(gi[0] + ghr);
            float z_  = sigmoidf_(gi[1] + ghz);
            float n_  = tanhf(gi[2] + r_ * ghn);
            float hn  = (1.0f - z_) * n_ + z_ * hp;
            g_h[b * 256 + j] = hn;
            out[(b * S_LEN + t) * 256 + j] = hn;
        }

        // ---- prefetch x(t+1) into zT x-region (overlaps C-reduce / bar) ----
        if (t + 1 < S_LEN) {
            for (int idx = tid; idx < 16 * 256; idx += NTHR) {
                int bb = idx >> 8, k = idx & 255;
                smf[OFF_Z + k * ZSTR + bb] =
                    x[((p * 16 + bb) * S_LEN + (t + 1)) * 256 + k];
            }
        }

        pbar(p);   // h_new published within batch group
    }
}

extern "C" void kernel_launch(void* const* d_in, const int* in_sizes, int n_in,
                              void* d_out, int out_size) {
    const float* x     = (const float*)d_in[0];
    const float* hid   = (const float*)d_in[1];
    const float* W_att = (const float*)d_in[2];
    const float* b_att = (const float*)d_in[3];
    const float* w_ih  = (const float*)d_in[4];
    const float* b_ih  = (const float*)d_in[5];
    const float* w_hh  = (const float*)d_in[6];
    const float* b_hh  = (const float*)d_in[7];
    float* out = (float*)d_out;

    cudaFuncSetAttribute(gru_att_persistent,
                         cudaFuncAttributeMaxDynamicSharedMemorySize, SMEM_BYTES);

    gru_att_persistent<<<NBLK, NTHR, SMEM_BYTES>>>(
        x, hid, W_att, b_att, w_ih, b_ih, w_hh, b_hh, out);
}